// round 9
// baseline (speedup 1.0000x reference)
#include <cuda_runtime.h>

#define TLEN 256
#define FULLMASK 0xffffffffu

#define OFF_Z   0u
#define OFF_MU  2097152u
#define OFF_SIG 4194304u
#define OFF_A   71303168u
#define OFF_AT  72351744u
#define OFF_BT  139460608u
#define OFF_CT  156237824u

#define NCHAIN 8           // chains (warps) per CTA
#define NTHR   (32 * NCHAIN)

struct SW {
    float4 AmT[1024];      // [k*32+row] = (A0..A3)[row][k]
    float4 CmS[512];       // [flat]
    float4 BmS[256];       // [flat]
    float4 BmT[256];       // [j*32+row]
    float  QT[1024];       // [j*32+row] = Q[row][j]
    float  Wh[64 * 192];
    float  Wx[32 * 192];
    float4 Wo4[64];
    float  bhs[192], bxs[192];
};
struct SC {                // per-chain scratch (one warp)
    float Ls[32 * 36];     // L rows; also A_t staging uses Gs below
    float Gs[32 * 36];     // staging for A_t, then G rows
    float Cts[32 * 17];    // [c*17+r] = C_t[r][c]
};
struct SAll { SW w; SC c[NCHAIN]; };

__device__ __forceinline__ float fast_tanh(float x) {
    float y; asm("tanh.approx.f32 %0, %1;" : "=f"(y) : "f"(x)); return y;
}
__device__ __forceinline__ float fast_sigmoid(float x) {
    return 0.5f + 0.5f * fast_tanh(0.5f * x);
}
__device__ __forceinline__ float mix4(float4 v, float a0, float a1, float a2, float a3) {
    return fmaf(v.x, a0, fmaf(v.y, a1, fmaf(v.z, a2, v.w * a3)));
}

// lane = row. a[] = own S row in; L rows -> Ls (upper zeroed).
// Returns z = zinit + L @ eps.
__device__ __forceinline__ float chol_ls(float a[32], float eps_own, float zinit,
                                         int lane, float* Ls)
{
    float zacc = zinit;
#pragma unroll
    for (int j = 0; j < 32; ++j) {
        float d   = __shfl_sync(FULLMASK, a[j], j);
        float rs  = rsqrtf(d);
        float lij = a[j] * rs;
        a[j] = lij;
        float ej = __shfl_sync(FULLMASK, eps_own, j);
        if (lane >= j) zacc = fmaf(lij, ej, zacc);
        float lsq = lij * lij;
#pragma unroll
        for (int k = j + 1; k < 32; ++k) {
            float lkj = __shfl_sync(FULLMASK, lij, k);
            if (k == lane) a[k] -= lsq;
            else           a[k] = fmaf(-lij, lkj, a[k]);
        }
    }
#pragma unroll
    for (int k = 0; k < 32; ++k) if (k > lane) a[k] = 0.f;
#pragma unroll
    for (int i = 0; i < 8; ++i)
        *(float4*)&Ls[lane * 36 + 4 * i] =
            make_float4(a[4*i], a[4*i+1], a[4*i+2], a[4*i+3]);
    return zacc;
}

__global__ void __launch_bounds__(NTHR, 1)
lgssm_kernel(const float* __restrict__ mu0,   const float* __restrict__ Sig0,
             const float* __restrict__ alpha0,const float* __restrict__ h0,
             const float* __restrict__ u_f,   const float* __restrict__ eps_g,
             const float* __restrict__ Ab,    const float* __restrict__ Bb,
             const float* __restrict__ Cb,    const float* __restrict__ Qm,
             const float* __restrict__ Wx,    const float* __restrict__ Wh,
             const float* __restrict__ bx,    const float* __restrict__ bh,
             const float* __restrict__ Wo,    const float* __restrict__ bo,
             float* __restrict__ out)
{
    extern __shared__ float smem_f[];
    SAll& sh = *reinterpret_cast<SAll*>(smem_f);

    const int tid  = threadIdx.x;
    const int lane = tid & 31;
    const int wid  = tid >> 5;

    // ---- one-time weight tables --------------------------------------------
    for (int i = tid; i < 1024; i += NTHR) {
        int k = i >> 5, row = i & 31, e = row * 32 + k;
        sh.w.AmT[i] = make_float4(Ab[e], Ab[1024 + e], Ab[2048 + e], Ab[3072 + e]);
        sh.w.QT[i]  = Qm[e];
    }
    for (int i = tid; i < 512; i += NTHR)
        sh.w.CmS[i] = make_float4(Cb[i], Cb[512 + i], Cb[1024 + i], Cb[1536 + i]);
    for (int i = tid; i < 256; i += NTHR) {
        sh.w.BmS[i] = make_float4(Bb[i], Bb[256 + i], Bb[512 + i], Bb[768 + i]);
        int j = i >> 5, row = i & 31, e = row * 8 + j;
        sh.w.BmT[i] = make_float4(Bb[e], Bb[256 + e], Bb[512 + e], Bb[768 + e]);
    }
    for (int i = tid; i < 64 * 192; i += NTHR) sh.w.Wh[i] = Wh[i];
    for (int i = tid; i < 32 * 192; i += NTHR) sh.w.Wx[i] = Wx[i];
    if (tid < 64) sh.w.Wo4[tid] = make_float4(Wo[tid*4], Wo[tid*4+1], Wo[tid*4+2], Wo[tid*4+3]);
    for (int i = tid; i < 192; i += NTHR) { sh.w.bhs[i] = bh[i]; sh.w.bxs[i] = bx[i]; }
    __syncthreads();

    // ---- per-chain (per-warp) state -----------------------------------------
    SC& C = sh.c[wid];
    const unsigned b = (unsigned)blockIdx.x * NCHAIN + (unsigned)wid;

    float mu_own = mu0[b * 32u + lane];
    float al0 = alpha0[b*4u+0], al1 = alpha0[b*4u+1];
    float al2 = alpha0[b*4u+2], al3 = alpha0[b*4u+3];
    float hown0 = h0[b*64u + lane], hown1 = h0[b*64u + 32 + lane];
    float bo0 = bo[0], bo1 = bo[1], bo2 = bo[2], bo3 = bo[3];

    {   // L0 = chol(Sigma0)
        float a[32];
#pragma unroll
        for (int i = 0; i < 8; ++i) {
            float4 v = *(const float4*)(Sig0 + b * 1024u + (unsigned)(lane * 32 + 4 * i));
            a[4*i] = v.x; a[4*i+1] = v.y; a[4*i+2] = v.z; a[4*i+3] = v.w;
        }
        (void)chol_ls(a, 0.f, 0.f, lane, C.Ls);
    }
    float ep_cur = eps_g[(b * TLEN) * 32u + lane];
    float u_cur  = (lane < 8) ? u_f[(b * TLEN) * 8u + lane] : 0.f;
    __syncwarp();

#pragma unroll 1
    for (int t = 0; t < TLEN; ++t) {
        const unsigned bt  = b * TLEN + (unsigned)t;
        const unsigned btn = bt + (t < TLEN - 1 ? 1u : 0u);
        float ep_nxt = eps_g[btn * 32u + lane];
        float u_nxt  = (lane < 8) ? u_f[btn * 8u + lane] : 0.f;

        __syncwarp();   // prev-step cross-lane reads of Ls/Gs done

        // ---- mixtures; stage A rows in Gs -----------------------------------
        float ar[32];
#pragma unroll 8
        for (int k = 0; k < 32; ++k)
            ar[k] = mix4(sh.w.AmT[k * 32 + lane], al0, al1, al2, al3);
#pragma unroll
        for (int i = 0; i < 8; ++i)
            *(float4*)&C.Gs[lane * 36 + 4 * i] =
                make_float4(ar[4*i], ar[4*i+1], ar[4*i+2], ar[4*i+3]);
#pragma unroll 4
        for (int e = 0; e < 16; ++e) {
            float cv = mix4(sh.w.CmS[e * 32 + lane], al0, al1, al2, al3);
            C.Cts[lane * 17 + e] = cv;
            out[OFF_CT + bt * 512u + (unsigned)(e * 32 + lane)] = cv;
        }
#pragma unroll
        for (int e = 0; e < 8; ++e)
            out[OFF_BT + bt * 256u + (unsigned)(e * 32 + lane)] =
                mix4(sh.w.BmS[e * 32 + lane], al0, al1, al2, al3);
        __syncwarp();   // staged A visible

        // ---- A_t out (coalesced, transposed read from staging) --------------
#pragma unroll 8
        for (int j = 0; j < 32; ++j)
            out[OFF_AT + bt * 1024u + (unsigned)(j * 32 + lane)] = C.Gs[j * 36 + lane];

        // ---- mu_next = A_t mu + B_t u ----------------------------------------
        float mu_new;
        {
            float m0 = 0.f, m1 = 0.f;
#pragma unroll 8
            for (int k = 0; k < 32; k += 2) {
                m0 = fmaf(ar[k],     __shfl_sync(FULLMASK, mu_own, k),     m0);
                m1 = fmaf(ar[k + 1], __shfl_sync(FULLMASK, mu_own, k + 1), m1);
            }
#pragma unroll
            for (int j = 0; j < 8; ++j) {
                float bj = mix4(sh.w.BmT[j * 32 + lane], al0, al1, al2, al3);
                m0 = fmaf(bj, __shfl_sync(FULLMASK, u_cur, j), m0);
            }
            mu_new = m0 + m1;
            out[OFF_MU + bt * 32u + lane] = mu_new;
        }
        __syncwarp();   // A_t reads done before G overwrites Gs

        // ---- G = A_t @ L ------------------------------------------------------
        float g[32];
#pragma unroll
        for (int j = 0; j < 32; ++j) g[j] = 0.f;
#pragma unroll 4
        for (int m = 0; m < 32; ++m) {
            float ak = ar[m];
            const float4* Lr = (const float4*)&C.Ls[m * 36];
#pragma unroll
            for (int i = 0; i < 8; ++i) {
                float4 lv = Lr[i];
                g[4*i+0] = fmaf(ak, lv.x, g[4*i+0]);
                g[4*i+1] = fmaf(ak, lv.y, g[4*i+1]);
                g[4*i+2] = fmaf(ak, lv.z, g[4*i+2]);
                g[4*i+3] = fmaf(ak, lv.w, g[4*i+3]);
            }
        }
#pragma unroll
        for (int i = 0; i < 8; ++i)
            *(float4*)&C.Gs[lane * 36 + 4 * i] =
                make_float4(g[4*i], g[4*i+1], g[4*i+2], g[4*i+3]);
        __syncwarp();   // G rows visible

        // ---- S = G G^T + Q (rows in regs); Sigma out -------------------------
        float sreg[32];
#pragma unroll 2
        for (int j = 0; j < 32; ++j) {
            const float4* Gr = (const float4*)&C.Gs[j * 36];
            float a0 = 0.f, a1 = 0.f, a2 = 0.f, a3 = 0.f;
#pragma unroll
            for (int i = 0; i < 8; ++i) {
                float4 gv = Gr[i];
                a0 = fmaf(g[4*i+0], gv.x, a0);
                a1 = fmaf(g[4*i+1], gv.y, a1);
                a2 = fmaf(g[4*i+2], gv.z, a2);
                a3 = fmaf(g[4*i+3], gv.w, a3);
            }
            sreg[j] = (a0 + a1) + (a2 + a3) + sh.w.QT[j * 32 + lane];
            out[OFF_SIG + bt * 1024u + (unsigned)(j * 32 + lane)] = sreg[j];
        }

        // ---- gh = h @ Wh + bh (independent; interleaves with chol) -----------
        float gha[6];
#pragma unroll
        for (int m = 0; m < 6; ++m) gha[m] = sh.w.bhs[lane + 32 * m];
#pragma unroll 4
        for (int hh = 0; hh < 32; ++hh) {
            float hv = __shfl_sync(FULLMASK, hown0, hh);
            const float* wr = &sh.w.Wh[hh * 192 + lane];
#pragma unroll
            for (int m = 0; m < 6; ++m) gha[m] = fmaf(hv, wr[32 * m], gha[m]);
        }
#pragma unroll 4
        for (int hh = 0; hh < 32; ++hh) {
            float hv = __shfl_sync(FULLMASK, hown1, hh);
            const float* wr = &sh.w.Wh[(hh + 32) * 192 + lane];
#pragma unroll
            for (int m = 0; m < 6; ++m) gha[m] = fmaf(hv, wr[32 * m], gha[m]);
        }

        // ---- chol(S) -> Ls, fused z ------------------------------------------
        float z_own = chol_ls(sreg, ep_cur, mu_new, lane, C.Ls);
        out[OFF_Z + bt * 32u + lane] = z_own;
        mu_own = mu_new;

        // ---- a_t = C_t z ------------------------------------------------------
        {
            float acc = 0.f;
#pragma unroll 8
            for (int k = 0; k < 32; ++k) {
                float zk = __shfl_sync(FULLMASK, z_own, k);
                acc = fmaf(C.Cts[k * 17 + (lane & 15)], zk, acc);
            }
            if (lane < 16) out[OFF_A + bt * 16u + lane] = acc;
        }

        // ---- gx = z @ Wx + bx -------------------------------------------------
        float gxa[6];
#pragma unroll
        for (int m = 0; m < 6; ++m) gxa[m] = sh.w.bxs[lane + 32 * m];
#pragma unroll 4
        for (int k = 0; k < 32; ++k) {
            float zk = __shfl_sync(FULLMASK, z_own, k);
            const float* wr = &sh.w.Wx[k * 192 + lane];
#pragma unroll
            for (int m = 0; m < 6; ++m) gxa[m] = fmaf(zk, wr[32 * m], gxa[m]);
        }

        // ---- GRU + replicated softmax ----------------------------------------
        {
            float r0 = fast_sigmoid(gxa[0] + gha[0]);
            float r1 = fast_sigmoid(gxa[1] + gha[1]);
            float zg0 = fast_sigmoid(gxa[2] + gha[2]);
            float zg1 = fast_sigmoid(gxa[3] + gha[3]);
            float n0 = fast_tanh(gxa[4] + r0 * gha[4]);
            float n1 = fast_tanh(gxa[5] + r1 * gha[5]);
            hown0 = (1.f - zg0) * n0 + zg0 * hown0;
            hown1 = (1.f - zg1) * n1 + zg1 * hown1;

            float4 w0 = sh.w.Wo4[lane], w1 = sh.w.Wo4[lane + 32];
            float p0 = fmaf(hown0, w0.x, hown1 * w1.x);
            float p1 = fmaf(hown0, w0.y, hown1 * w1.y);
            float p2 = fmaf(hown0, w0.z, hown1 * w1.z);
            float p3 = fmaf(hown0, w0.w, hown1 * w1.w);
#pragma unroll
            for (int off = 16; off; off >>= 1) {
                p0 += __shfl_xor_sync(FULLMASK, p0, off);
                p1 += __shfl_xor_sync(FULLMASK, p1, off);
                p2 += __shfl_xor_sync(FULLMASK, p2, off);
                p3 += __shfl_xor_sync(FULLMASK, p3, off);
            }
            float o0 = p0 + bo0, o1 = p1 + bo1, o2 = p2 + bo2, o3 = p3 + bo3;
            float mx = fmaxf(fmaxf(o0, o1), fmaxf(o2, o3));
            float e0 = __expf(o0 - mx), e1 = __expf(o1 - mx);
            float e2 = __expf(o2 - mx), e3 = __expf(o3 - mx);
            float inv = 1.f / (e0 + e1 + e2 + e3);
            al0 = e0 * inv; al1 = e1 * inv; al2 = e2 * inv; al3 = e3 * inv;
        }

        ep_cur = ep_nxt;
        u_cur  = u_nxt;
    }
}

extern "C" void kernel_launch(void* const* d_in, const int* in_sizes, int n_in,
                              void* d_out, int out_size)
{
    size_t shbytes = sizeof(SAll);
    cudaFuncSetAttribute(lgssm_kernel,
                         cudaFuncAttributeMaxDynamicSharedMemorySize, (int)shbytes);
    lgssm_kernel<<<256 / NCHAIN, NTHR, shbytes>>>(
        (const float*)d_in[0],  (const float*)d_in[1],  (const float*)d_in[2],
        (const float*)d_in[3],  (const float*)d_in[4],  (const float*)d_in[5],
        (const float*)d_in[6],  (const float*)d_in[7],  (const float*)d_in[8],
        (const float*)d_in[9],  (const float*)d_in[10], (const float*)d_in[11],
        (const float*)d_in[12], (const float*)d_in[13], (const float*)d_in[14],
        (const float*)d_in[15], (float*)d_out);
}

// round 11
// speedup vs baseline: 2.8794x; 2.8794x over previous
#include <cuda_runtime.h>

#define TLEN 256
#define FULLMASK 0xffffffffu

#define OFF_Z   0u
#define OFF_MU  2097152u
#define OFF_SIG 4194304u
#define OFF_A   71303168u
#define OFF_AT  72351744u
#define OFF_BT  139460608u
#define OFF_CT  156237824u

struct SW {
    float4 AmT[1024];      // [k*32+row] = (A0..A3)[row][k]
    float4 CmS[512];       // [flat]
    float4 BmS[256];       // [flat]
    float4 BmT[256];       // [j*32+row]
    float  QT[1024];       // [k*32+row] = Q[row][k]
    float  Wh[64 * 192];
    float  Wx[32 * 192];
    float4 Wo4[64];
    float  bhs[192], bxs[192];
};
struct SC {
    float Ls[32 * 36];     // L rows (float4, 36%4==0)
    float Gs[32 * 36];     // G rows
    float As[32 * 33];     // scalar only (pad 33: conflict-free)
    float Ss0[32 * 33];    // S partial k>=16 (spine)  — scalar only
    float Ss1[32 * 33];    // S partial k<16  (helper) — scalar only
    float Cts[32 * 17];    // [c*17+r] = C_t[r][c]
    float zs[32];
    float alsh[4];
};
struct SAll { SW w; SC c[2]; };

__device__ __forceinline__ float fast_tanh(float x) {
    float y; asm("tanh.approx.f32 %0, %1;" : "=f"(y) : "f"(x)); return y;
}
__device__ __forceinline__ float fast_sigmoid(float x) {
    return 0.5f + 0.5f * fast_tanh(0.5f * x);
}
__device__ __forceinline__ float mix4(float4 v, float a0, float a1, float a2, float a3) {
    return fmaf(v.x, a0, fmaf(v.y, a1, fmaf(v.z, a2, v.w * a3)));
}

__device__ __forceinline__ float chol_ls(float a[32], float eps_own, float zinit,
                                         int lane, float* Ls)
{
    float zacc = zinit;
#pragma unroll
    for (int j = 0; j < 32; ++j) {
        float d   = __shfl_sync(FULLMASK, a[j], j);
        float rs  = rsqrtf(d);
        float lij = a[j] * rs;
        a[j] = lij;
        float ej = __shfl_sync(FULLMASK, eps_own, j);
        if (lane >= j) zacc = fmaf(lij, ej, zacc);
        float lsq = lij * lij;
#pragma unroll
        for (int k = j + 1; k < 32; ++k) {
            float lkj = __shfl_sync(FULLMASK, lij, k);
            if (k == lane) a[k] -= lsq;
            else           a[k] = fmaf(-lij, lkj, a[k]);
        }
    }
#pragma unroll
    for (int k = 0; k < 32; ++k) if (k > lane) a[k] = 0.f;
#pragma unroll
    for (int i = 0; i < 8; ++i)
        *(float4*)&Ls[lane * 36 + 4 * i] =
            make_float4(a[4*i], a[4*i+1], a[4*i+2], a[4*i+3]);
    return zacc;
}

__global__ void __launch_bounds__(128, 1)
lgssm_kernel(const float* __restrict__ mu0,   const float* __restrict__ Sig0,
             const float* __restrict__ alpha0,const float* __restrict__ h0,
             const float* __restrict__ u_f,   const float* __restrict__ eps_g,
             const float* __restrict__ Ab,    const float* __restrict__ Bb,
             const float* __restrict__ Cb,    const float* __restrict__ Qm,
             const float* __restrict__ Wx,    const float* __restrict__ Wh,
             const float* __restrict__ bx,    const float* __restrict__ bh,
             const float* __restrict__ Wo,    const float* __restrict__ bo,
             float* __restrict__ out)
{
    extern __shared__ float smem_f[];
    SAll& sh = *reinterpret_cast<SAll*>(smem_f);

    const int tid   = threadIdx.x;
    const int lane  = tid & 31;
    const int wid   = tid >> 5;
    const int chain = wid >> 1;
    const int cw    = wid & 1;          // 0 = spine (chol), 1 = helper
    const int barid = chain + 1;
    SC& C = sh.c[chain];
    const unsigned b = (unsigned)blockIdx.x * 2u + (unsigned)chain;

#define CBAR() asm volatile("bar.sync %0, 64;" :: "r"(barid) : "memory")

    // ---- one-time weight tables ---------------------------------------------
    for (int i = tid; i < 1024; i += 128) {
        int k = i >> 5, row = i & 31, e = row * 32 + k;
        sh.w.AmT[i] = make_float4(Ab[e], Ab[1024 + e], Ab[2048 + e], Ab[3072 + e]);
        sh.w.QT[i]  = Qm[e];
    }
    for (int i = tid; i < 512; i += 128)
        sh.w.CmS[i] = make_float4(Cb[i], Cb[512 + i], Cb[1024 + i], Cb[1536 + i]);
    for (int i = tid; i < 256; i += 128) {
        sh.w.BmS[i] = make_float4(Bb[i], Bb[256 + i], Bb[512 + i], Bb[768 + i]);
        int j = i >> 5, row = i & 31, e = row * 8 + j;
        sh.w.BmT[i] = make_float4(Bb[e], Bb[256 + e], Bb[512 + e], Bb[768 + e]);
    }
    for (int i = tid; i < 64 * 192; i += 128) sh.w.Wh[i] = Wh[i];
    for (int i = tid; i < 32 * 192; i += 128) sh.w.Wx[i] = Wx[i];
    if (tid < 64) sh.w.Wo4[tid] = make_float4(Wo[tid*4], Wo[tid*4+1], Wo[tid*4+2], Wo[tid*4+3]);
    for (int i = tid; i < 192; i += 128) { sh.w.bhs[i] = bh[i]; sh.w.bxs[i] = bx[i]; }

    // ---- per-chain state -----------------------------------------------------
    float al0 = alpha0[b*4u+0], al1 = alpha0[b*4u+1];
    float al2 = alpha0[b*4u+2], al3 = alpha0[b*4u+3];
    float mu_own = 0.f, ep_cur = 0.f, u_cur = 0.f;
    float hown0 = 0.f, hown1 = 0.f, bo0 = 0.f, bo1 = 0.f, bo2 = 0.f, bo3 = 0.f;

    if (cw == 0) {
        mu_own = mu0[b * 32u + lane];
        ep_cur = eps_g[(b * TLEN) * 32u + lane];
        u_cur  = (lane < 8) ? u_f[(b * TLEN) * 8u + lane] : 0.f;
    } else {
        hown0 = h0[b*64u + lane]; hown1 = h0[b*64u + 32 + lane];
        bo0 = bo[0]; bo1 = bo[1]; bo2 = bo[2]; bo3 = bo[3];
    }
    __syncthreads();
    if (cw == 0) {                       // L0 = chol(Sigma0)
        float a[32];
#pragma unroll
        for (int i = 0; i < 8; ++i) {
            float4 v = *(const float4*)(Sig0 + b * 1024u + (unsigned)(lane * 32 + 4 * i));
            a[4*i] = v.x; a[4*i+1] = v.y; a[4*i+2] = v.z; a[4*i+3] = v.w;
        }
        (void)chol_ls(a, 0.f, 0.f, lane, C.Ls);
    }
    __syncthreads();

#pragma unroll 1
    for (int t = 0; t < TLEN; ++t) {
        const unsigned bt  = b * TLEN + (unsigned)t;
        const unsigned btn = bt + (t < TLEN - 1 ? 1u : 0u);
        float ar[32], g[16], sregH[32];
        float mu_new = 0.f, z_own = 0.f, ep_nxt = 0.f, u_nxt = 0.f, gha[6];

        // ===== P0: spine A-mixture -> As; helper C/B mixtures + outs ==========
        if (cw == 0) {
            ep_nxt = eps_g[btn * 32u + lane];
            u_nxt  = (lane < 8) ? u_f[btn * 8u + lane] : 0.f;
#pragma unroll 8
            for (int k = 0; k < 32; ++k) {
                ar[k] = mix4(sh.w.AmT[k * 32 + lane], al0, al1, al2, al3);
                C.As[lane * 33 + k] = ar[k];
            }
        } else {
#pragma unroll 4
            for (int e = 0; e < 16; ++e) {
                float cv = mix4(sh.w.CmS[e * 32 + lane], al0, al1, al2, al3);
                C.Cts[lane * 17 + e] = cv;
                out[OFF_CT + bt * 512u + (unsigned)(e * 32 + lane)] = cv;
            }
#pragma unroll
            for (int e = 0; e < 8; ++e)
                out[OFF_BT + bt * 256u + (unsigned)(e * 32 + lane)] =
                    mix4(sh.w.BmS[e * 32 + lane], al0, al1, al2, al3);
        }
        CBAR();

        // ===== P1: mu + triangular G halves + S partials + A_t out ============
        if (cw == 0) {
            float m0 = 0.f, m1 = 0.f;
#pragma unroll 8
            for (int k = 0; k < 32; k += 2) {
                m0 = fmaf(ar[k],     __shfl_sync(FULLMASK, mu_own, k),     m0);
                m1 = fmaf(ar[k + 1], __shfl_sync(FULLMASK, mu_own, k + 1), m1);
            }
#pragma unroll
            for (int j = 0; j < 8; ++j) {
                float bj = mix4(sh.w.BmT[j * 32 + lane], al0, al1, al2, al3);
                m0 = fmaf(bj, __shfl_sync(FULLMASK, u_cur, j), m0);
            }
            mu_new = m0 + m1;
            out[OFF_MU + bt * 32u + lane] = mu_new;
            // G cols 16..31; L triangular -> k >= 16+4jb
#pragma unroll
            for (int i = 0; i < 16; ++i) g[i] = 0.f;
#pragma unroll
            for (int jb = 0; jb < 4; ++jb) {
                for (int k = 16 + 4 * jb; k < 32; ++k) {
                    float ak = ar[k];
                    float4 lv = *(const float4*)&C.Ls[k * 36 + 16 + 4 * jb];
                    g[4*jb+0] = fmaf(ak, lv.x, g[4*jb+0]);
                    g[4*jb+1] = fmaf(ak, lv.y, g[4*jb+1]);
                    g[4*jb+2] = fmaf(ak, lv.z, g[4*jb+2]);
                    g[4*jb+3] = fmaf(ak, lv.w, g[4*jb+3]);
                }
            }
#pragma unroll
            for (int i = 0; i < 4; ++i)
                *(float4*)&C.Gs[lane * 36 + 16 + 4 * i] =
                    make_float4(g[4*i], g[4*i+1], g[4*i+2], g[4*i+3]);
            __syncwarp();
#pragma unroll 2
            for (int j = 0; j < 32; ++j) {            // S partial, k in 16..31
                const float4* Gr = (const float4*)&C.Gs[j * 36 + 16];
                float a0 = 0.f, a1 = 0.f, a2 = 0.f, a3 = 0.f;
#pragma unroll
                for (int i = 0; i < 4; ++i) {
                    float4 gv = Gr[i];
                    a0 = fmaf(g[4*i+0], gv.x, a0);
                    a1 = fmaf(g[4*i+1], gv.y, a1);
                    a2 = fmaf(g[4*i+2], gv.z, a2);
                    a3 = fmaf(g[4*i+3], gv.w, a3);
                }
                sregH[j] = (a0 + a1) + (a2 + a3);
                C.Ss0[lane * 33 + j] = sregH[j];
            }
        } else {
#pragma unroll 8
            for (int j = 0; j < 32; ++j)               // A_t out (scalar, coalesced)
                out[OFF_AT + bt * 1024u + (unsigned)(j * 32 + lane)] = C.As[j * 33 + lane];
            // G cols 0..15; k >= 4jb
#pragma unroll
            for (int i = 0; i < 16; ++i) g[i] = 0.f;
#pragma unroll
            for (int jb = 0; jb < 4; ++jb) {
                for (int k = 4 * jb; k < 32; ++k) {
                    float ak = C.As[lane * 33 + k];
                    float4 lv = *(const float4*)&C.Ls[k * 36 + 4 * jb];
                    g[4*jb+0] = fmaf(ak, lv.x, g[4*jb+0]);
                    g[4*jb+1] = fmaf(ak, lv.y, g[4*jb+1]);
                    g[4*jb+2] = fmaf(ak, lv.z, g[4*jb+2]);
                    g[4*jb+3] = fmaf(ak, lv.w, g[4*jb+3]);
                }
            }
#pragma unroll
            for (int i = 0; i < 4; ++i)
                *(float4*)&C.Gs[lane * 36 + 4 * i] =
                    make_float4(g[4*i], g[4*i+1], g[4*i+2], g[4*i+3]);
            __syncwarp();
#pragma unroll 2
            for (int j = 0; j < 32; ++j) {            // S partial, k in 0..15
                const float4* Gr = (const float4*)&C.Gs[j * 36];
                float a0 = 0.f, a1 = 0.f, a2 = 0.f, a3 = 0.f;
#pragma unroll
                for (int i = 0; i < 4; ++i) {
                    float4 gv = Gr[i];
                    a0 = fmaf(g[4*i+0], gv.x, a0);
                    a1 = fmaf(g[4*i+1], gv.y, a1);
                    a2 = fmaf(g[4*i+2], gv.z, a2);
                    a3 = fmaf(g[4*i+3], gv.w, a3);
                }
                sregH[j] = (a0 + a1) + (a2 + a3);     // helper: k<16 partial
                C.Ss1[lane * 33 + j] = sregH[j];
            }
        }
        CBAR();

        // ===== P2: spine chol(+z); helper Sigma out + gh =======================
        if (cw == 0) {
            float a[32];
#pragma unroll 8
            for (int k = 0; k < 32; ++k)
                a[k] = sregH[k] + C.Ss1[lane * 33 + k] + sh.w.QT[k * 32 + lane];
            z_own = chol_ls(a, ep_cur, mu_new, lane, C.Ls);
            out[OFF_Z + bt * 32u + lane] = z_own;
            C.zs[lane] = z_own;
            mu_own = mu_new;
            ep_cur = ep_nxt; u_cur = u_nxt;
        } else {
#pragma unroll 4
            for (int j = 0; j < 32; ++j)               // Σ out: own regs + Ss0
                out[OFF_SIG + bt * 1024u + (unsigned)(j * 32 + lane)] =
                    sregH[j] + C.Ss0[lane * 33 + j] + sh.w.QT[j * 32 + lane];
#pragma unroll
            for (int m = 0; m < 6; ++m) gha[m] = sh.w.bhs[lane + 32 * m];
#pragma unroll 4
            for (int hh = 0; hh < 32; ++hh) {
                float hv = __shfl_sync(FULLMASK, hown0, hh);
                const float* wr = &sh.w.Wh[hh * 192 + lane];
#pragma unroll
                for (int m = 0; m < 6; ++m) gha[m] = fmaf(hv, wr[32 * m], gha[m]);
            }
#pragma unroll 4
            for (int hh = 0; hh < 32; ++hh) {
                float hv = __shfl_sync(FULLMASK, hown1, hh);
                const float* wr = &sh.w.Wh[(hh + 32) * 192 + lane];
#pragma unroll
                for (int m = 0; m < 6; ++m) gha[m] = fmaf(hv, wr[32 * m], gha[m]);
            }
        }
        CBAR();

        // ===== P3: spine a_t; helper gx + GRU + softmax ========================
        if (cw == 0) {
            float acc = 0.f;
#pragma unroll 8
            for (int k = 0; k < 32; ++k) {
                float zk = __shfl_sync(FULLMASK, z_own, k);
                acc = fmaf(C.Cts[k * 17 + (lane & 15)], zk, acc);
            }
            if (lane < 16) out[OFF_A + bt * 16u + lane] = acc;
        } else {
            float z1 = C.zs[lane];
            float gxa[6];
#pragma unroll
            for (int m = 0; m < 6; ++m) gxa[m] = sh.w.bxs[lane + 32 * m];
#pragma unroll 4
            for (int k = 0; k < 32; ++k) {
                float zk = __shfl_sync(FULLMASK, z1, k);
                const float* wr = &sh.w.Wx[k * 192 + lane];
#pragma unroll
                for (int m = 0; m < 6; ++m) gxa[m] = fmaf(zk, wr[32 * m], gxa[m]);
            }
            float r0 = fast_sigmoid(gxa[0] + gha[0]);
            float r1 = fast_sigmoid(gxa[1] + gha[1]);
            float zg0 = fast_sigmoid(gxa[2] + gha[2]);
            float zg1 = fast_sigmoid(gxa[3] + gha[3]);
            float n0 = fast_tanh(gxa[4] + r0 * gha[4]);
            float n1 = fast_tanh(gxa[5] + r1 * gha[5]);
            hown0 = (1.f - zg0) * n0 + zg0 * hown0;
            hown1 = (1.f - zg1) * n1 + zg1 * hown1;
            float4 w0 = sh.w.Wo4[lane], w1 = sh.w.Wo4[lane + 32];
            float p0 = fmaf(hown0, w0.x, hown1 * w1.x);
            float p1 = fmaf(hown0, w0.y, hown1 * w1.y);
            float p2 = fmaf(hown0, w0.z, hown1 * w1.z);
            float p3 = fmaf(hown0, w0.w, hown1 * w1.w);
#pragma unroll
            for (int off = 16; off; off >>= 1) {
                p0 += __shfl_xor_sync(FULLMASK, p0, off);
                p1 += __shfl_xor_sync(FULLMASK, p1, off);
                p2 += __shfl_xor_sync(FULLMASK, p2, off);
                p3 += __shfl_xor_sync(FULLMASK, p3, off);
            }
            float o0 = p0 + bo0, o1 = p1 + bo1, o2 = p2 + bo2, o3 = p3 + bo3;
            float mx = fmaxf(fmaxf(o0, o1), fmaxf(o2, o3));
            float e0 = __expf(o0 - mx), e1 = __expf(o1 - mx);
            float e2 = __expf(o2 - mx), e3 = __expf(o3 - mx);
            float inv = 1.f / (e0 + e1 + e2 + e3);
            if (lane == 0) {
                C.alsh[0] = e0 * inv; C.alsh[1] = e1 * inv;
                C.alsh[2] = e2 * inv; C.alsh[3] = e3 * inv;
            }
        }
        CBAR();
        al0 = C.alsh[0]; al1 = C.alsh[1]; al2 = C.alsh[2]; al3 = C.alsh[3];
    }
#undef CBAR
}

extern "C" void kernel_launch(void* const* d_in, const int* in_sizes, int n_in,
                              void* d_out, int out_size)
{
    size_t shbytes = sizeof(SAll);
    cudaFuncSetAttribute(lgssm_kernel,
                         cudaFuncAttributeMaxDynamicSharedMemorySize, (int)shbytes);
    lgssm_kernel<<<128, 128, shbytes>>>(
        (const float*)d_in[0],  (const float*)d_in[1],  (const float*)d_in[2],
        (const float*)d_in[3],  (const float*)d_in[4],  (const float*)d_in[5],
        (const float*)d_in[6],  (const float*)d_in[7],  (const float*)d_in[8],
        (const float*)d_in[9],  (const float*)d_in[10], (const float*)d_in[11],
        (const float*)d_in[12], (const float*)d_in[13], (const float*)d_in[14],
        (const float*)d_in[15], (float*)d_out);
}

// round 12
// speedup vs baseline: 3.0575x; 1.0619x over previous
#include <cuda_runtime.h>

#define TLEN 256
#define FULLMASK 0xffffffffu

#define OFF_Z   0u
#define OFF_MU  2097152u
#define OFF_SIG 4194304u
#define OFF_A   71303168u
#define OFF_AT  72351744u
#define OFF_BT  139460608u
#define OFF_CT  156237824u

struct SW {
    float4 AmT[1024];      // [k*32+row] = (A0..A3)[row][k]
    float4 CmS[512];       // [flat]
    float4 BmS[256];       // [flat]
    float4 BmT[256];       // [j*32+row]
    float  QT[1024];       // [k*32+row] = Q[row][k]
    float  Wh[64 * 192];
    float  Wx[32 * 192];
    float4 Wo4[64];
    float  bhs[192], bxs[192];
};
struct SC {
    float Ls[32 * 36];     // L rows (float4-aligned pad)
    float Gs[32 * 36];     // G rows
    float As[32 * 33];     // scalar, conflict-free pad
    float Ss1[32 * 33];    // helper's S partial (k<16), scalar
    float Cts[32 * 17];    // [c*17+r] = C_t[r][c]
    float zs[32];
    float alsh[4];
};
struct SAll { SW w; SC c[2]; };

__device__ __forceinline__ float fast_tanh(float x) {
    float y; asm("tanh.approx.f32 %0, %1;" : "=f"(y) : "f"(x)); return y;
}
__device__ __forceinline__ float fast_sigmoid(float x) {
    return 0.5f + 0.5f * fast_tanh(0.5f * x);
}
__device__ __forceinline__ float mix4(float4 v, float a0, float a1, float a2, float a3) {
    return fmaf(v.x, a0, fmaf(v.y, a1, fmaf(v.z, a2, v.w * a3)));
}

// Fully-unrolled warp Cholesky; a[] in registers throughout.
__device__ __forceinline__ float chol_ls(float a[32], float eps_own, float zinit,
                                         int lane, float* Ls)
{
    float zacc = zinit;
#pragma unroll
    for (int j = 0; j < 32; ++j) {
        float d   = __shfl_sync(FULLMASK, a[j], j);
        float rs  = rsqrtf(d);
        float lij = a[j] * rs;
        a[j] = lij;
        float ej = __shfl_sync(FULLMASK, eps_own, j);
        if (lane >= j) zacc = fmaf(lij, ej, zacc);
        float lsq = lij * lij;
#pragma unroll
        for (int k = j + 1; k < 32; ++k) {
            float lkj = __shfl_sync(FULLMASK, lij, k);
            if (k == lane) a[k] -= lsq;
            else           a[k] = fmaf(-lij, lkj, a[k]);
        }
    }
#pragma unroll
    for (int k = 0; k < 32; ++k) if (k > lane) a[k] = 0.f;
#pragma unroll
    for (int i = 0; i < 8; ++i)
        *(float4*)&Ls[lane * 36 + 4 * i] =
            make_float4(a[4*i], a[4*i+1], a[4*i+2], a[4*i+3]);
    return zacc;
}

__global__ void __launch_bounds__(128, 1)
lgssm_kernel(const float* __restrict__ mu0,   const float* __restrict__ Sig0,
             const float* __restrict__ alpha0,const float* __restrict__ h0,
             const float* __restrict__ u_f,   const float* __restrict__ eps_g,
             const float* __restrict__ Ab,    const float* __restrict__ Bb,
             const float* __restrict__ Cb,    const float* __restrict__ Qm,
             const float* __restrict__ Wx,    const float* __restrict__ Wh,
             const float* __restrict__ bx,    const float* __restrict__ bh,
             const float* __restrict__ Wo,    const float* __restrict__ bo,
             float* __restrict__ out)
{
    extern __shared__ float smem_f[];
    SAll& sh = *reinterpret_cast<SAll*>(smem_f);

    const int tid   = threadIdx.x;
    const int lane  = tid & 31;
    const int wid   = tid >> 5;
    const int chain = wid >> 1;
    const int cw    = wid & 1;          // 0 = spine (chol), 1 = helper
    const int barid = chain + 1;
    SC& C = sh.c[chain];
    const unsigned b = (unsigned)blockIdx.x * 2u + (unsigned)chain;

#define CBAR() asm volatile("bar.sync %0, 64;" :: "r"(barid) : "memory")

    // ---- one-time weight tables ---------------------------------------------
    for (int i = tid; i < 1024; i += 128) {
        int k = i >> 5, row = i & 31, e = row * 32 + k;
        sh.w.AmT[i] = make_float4(Ab[e], Ab[1024 + e], Ab[2048 + e], Ab[3072 + e]);
        sh.w.QT[i]  = Qm[e];
    }
    for (int i = tid; i < 512; i += 128)
        sh.w.CmS[i] = make_float4(Cb[i], Cb[512 + i], Cb[1024 + i], Cb[1536 + i]);
    for (int i = tid; i < 256; i += 128) {
        sh.w.BmS[i] = make_float4(Bb[i], Bb[256 + i], Bb[512 + i], Bb[768 + i]);
        int j = i >> 5, row = i & 31, e = row * 8 + j;
        sh.w.BmT[i] = make_float4(Bb[e], Bb[256 + e], Bb[512 + e], Bb[768 + e]);
    }
    for (int i = tid; i < 64 * 192; i += 128) sh.w.Wh[i] = Wh[i];
    for (int i = tid; i < 32 * 192; i += 128) sh.w.Wx[i] = Wx[i];
    if (tid < 64) sh.w.Wo4[tid] = make_float4(Wo[tid*4], Wo[tid*4+1], Wo[tid*4+2], Wo[tid*4+3]);
    for (int i = tid; i < 192; i += 128) { sh.w.bhs[i] = bh[i]; sh.w.bxs[i] = bx[i]; }

    // ---- per-chain state -----------------------------------------------------
    float al0 = alpha0[b*4u+0], al1 = alpha0[b*4u+1];
    float al2 = alpha0[b*4u+2], al3 = alpha0[b*4u+3];
    float mu_own = 0.f, ep_cur = 0.f, u_cur = 0.f;
    float hown0 = 0.f, hown1 = 0.f, bo0 = 0.f, bo1 = 0.f, bo2 = 0.f, bo3 = 0.f;
    float qrow[32];                      // spine: Q row resident in registers

    if (cw == 0) {
        mu_own = mu0[b * 32u + lane];
        ep_cur = eps_g[(b * TLEN) * 32u + lane];
        u_cur  = (lane < 8) ? u_f[(b * TLEN) * 8u + lane] : 0.f;
#pragma unroll
        for (int k = 0; k < 32; ++k) qrow[k] = sh.w.QT[k * 32 + lane];  // after CTA fill? no—
    } else {
        hown0 = h0[b*64u + lane]; hown1 = h0[b*64u + 32 + lane];
        bo0 = bo[0]; bo1 = bo[1]; bo2 = bo[2]; bo3 = bo[3];
    }
    __syncthreads();
    if (cw == 0) {
#pragma unroll
        for (int k = 0; k < 32; ++k) qrow[k] = sh.w.QT[k * 32 + lane];  // re-read post-sync (safe)
        float a[32];
#pragma unroll
        for (int i = 0; i < 8; ++i) {
            float4 v = *(const float4*)(Sig0 + b * 1024u + (unsigned)(lane * 32 + 4 * i));
            a[4*i] = v.x; a[4*i+1] = v.y; a[4*i+2] = v.z; a[4*i+3] = v.w;
        }
        (void)chol_ls(a, 0.f, 0.f, lane, C.Ls);
    }
    __syncthreads();

#pragma unroll 1
    for (int t = 0; t < TLEN; ++t) {
        const unsigned bt  = b * TLEN + (unsigned)t;
        const unsigned btn = bt + (t < TLEN - 1 ? 1u : 0u);
        float ar[32], g[16], sregH[32], gha[6];
        float mu_new = 0.f, z_own = 0.f, ep_nxt = 0.f, u_nxt = 0.f;

        // ===== P0: spine A-mixture (regs + As); helper C/B mixtures ==========
        if (cw == 0) {
            ep_nxt = eps_g[btn * 32u + lane];
            u_nxt  = (lane < 8) ? u_f[btn * 8u + lane] : 0.f;
#pragma unroll
            for (int k = 0; k < 32; ++k) {
                ar[k] = mix4(sh.w.AmT[k * 32 + lane], al0, al1, al2, al3);
                C.As[lane * 33 + k] = ar[k];
            }
        } else {
#pragma unroll
            for (int e = 0; e < 16; ++e) {
                float cv = mix4(sh.w.CmS[e * 32 + lane], al0, al1, al2, al3);
                C.Cts[lane * 17 + e] = cv;
                out[OFF_CT + bt * 512u + (unsigned)(e * 32 + lane)] = cv;
            }
#pragma unroll
            for (int e = 0; e < 8; ++e)
                out[OFF_BT + bt * 256u + (unsigned)(e * 32 + lane)] =
                    mix4(sh.w.BmS[e * 32 + lane], al0, al1, al2, al3);
        }
        CBAR();

        // ===== P1: spine mu + A_t(regs) + G-high + S-high; helper G/S-low ====
        if (cw == 0) {
            float m0 = 0.f, m1 = 0.f;
#pragma unroll
            for (int k = 0; k < 32; k += 2) {
                m0 = fmaf(ar[k],     __shfl_sync(FULLMASK, mu_own, k),     m0);
                m1 = fmaf(ar[k + 1], __shfl_sync(FULLMASK, mu_own, k + 1), m1);
            }
#pragma unroll
            for (int j = 0; j < 8; ++j) {
                float bj = mix4(sh.w.BmT[j * 32 + lane], al0, al1, al2, al3);
                m0 = fmaf(bj, __shfl_sync(FULLMASK, u_cur, j), m0);
            }
            mu_new = m0 + m1;
            out[OFF_MU + bt * 32u + lane] = mu_new;
            // A_t out straight from registers (row-major, 8x STG.128)
#pragma unroll
            for (int i = 0; i < 8; ++i)
                *(float4*)(out + OFF_AT + bt * 1024u + (unsigned)(lane * 32 + 4 * i)) =
                    make_float4(ar[4*i], ar[4*i+1], ar[4*i+2], ar[4*i+3]);
            // G cols 16..31 (triangular: k >= 16+4jb), fully unrolled
#pragma unroll
            for (int i = 0; i < 16; ++i) g[i] = 0.f;
#pragma unroll
            for (int jb = 0; jb < 4; ++jb) {
#pragma unroll
                for (int k = 16 + 4 * jb; k < 32; ++k) {
                    float ak = ar[k];
                    float4 lv = *(const float4*)&C.Ls[k * 36 + 16 + 4 * jb];
                    g[4*jb+0] = fmaf(ak, lv.x, g[4*jb+0]);
                    g[4*jb+1] = fmaf(ak, lv.y, g[4*jb+1]);
                    g[4*jb+2] = fmaf(ak, lv.z, g[4*jb+2]);
                    g[4*jb+3] = fmaf(ak, lv.w, g[4*jb+3]);
                }
            }
#pragma unroll
            for (int i = 0; i < 4; ++i)
                *(float4*)&C.Gs[lane * 36 + 16 + 4 * i] =
                    make_float4(g[4*i], g[4*i+1], g[4*i+2], g[4*i+3]);
            __syncwarp();
#pragma unroll
            for (int j = 0; j < 32; ++j) {            // S partial (k 16..31) -> regs
                const float4* Gr = (const float4*)&C.Gs[j * 36 + 16];
                float a0 = 0.f, a1 = 0.f, a2 = 0.f, a3 = 0.f;
#pragma unroll
                for (int i = 0; i < 4; ++i) {
                    float4 gv = Gr[i];
                    a0 = fmaf(g[4*i+0], gv.x, a0);
                    a1 = fmaf(g[4*i+1], gv.y, a1);
                    a2 = fmaf(g[4*i+2], gv.z, a2);
                    a3 = fmaf(g[4*i+3], gv.w, a3);
                }
                sregH[j] = (a0 + a1) + (a2 + a3);
            }
        } else {
            // G cols 0..15 (k >= 4jb)
#pragma unroll
            for (int i = 0; i < 16; ++i) g[i] = 0.f;
#pragma unroll
            for (int jb = 0; jb < 4; ++jb) {
#pragma unroll
                for (int k = 4 * jb; k < 32; ++k) {
                    float ak = C.As[lane * 33 + k];
                    float4 lv = *(const float4*)&C.Ls[k * 36 + 4 * jb];
                    g[4*jb+0] = fmaf(ak, lv.x, g[4*jb+0]);
                    g[4*jb+1] = fmaf(ak, lv.y, g[4*jb+1]);
                    g[4*jb+2] = fmaf(ak, lv.z, g[4*jb+2]);
                    g[4*jb+3] = fmaf(ak, lv.w, g[4*jb+3]);
                }
            }
#pragma unroll
            for (int i = 0; i < 4; ++i)
                *(float4*)&C.Gs[lane * 36 + 4 * i] =
                    make_float4(g[4*i], g[4*i+1], g[4*i+2], g[4*i+3]);
            __syncwarp();
#pragma unroll
            for (int j = 0; j < 32; ++j) {            // S partial (k 0..15) -> Ss1
                const float4* Gr = (const float4*)&C.Gs[j * 36];
                float a0 = 0.f, a1 = 0.f, a2 = 0.f, a3 = 0.f;
#pragma unroll
                for (int i = 0; i < 4; ++i) {
                    float4 gv = Gr[i];
                    a0 = fmaf(g[4*i+0], gv.x, a0);
                    a1 = fmaf(g[4*i+1], gv.y, a1);
                    a2 = fmaf(g[4*i+2], gv.z, a2);
                    a3 = fmaf(g[4*i+3], gv.w, a3);
                }
                C.Ss1[lane * 33 + j] = (a0 + a1) + (a2 + a3);
            }
        }
        CBAR();

        // ===== P2: spine S assemble + Sigma out(regs) + chol; helper gh ======
        if (cw == 0) {
#pragma unroll
            for (int k = 0; k < 32; ++k)
                sregH[k] += C.Ss1[lane * 33 + k] + qrow[k];
#pragma unroll
            for (int i = 0; i < 8; ++i)               // Sigma out (symmetric, row-major)
                *(float4*)(out + OFF_SIG + bt * 1024u + (unsigned)(lane * 32 + 4 * i)) =
                    make_float4(sregH[4*i], sregH[4*i+1], sregH[4*i+2], sregH[4*i+3]);
            z_own = chol_ls(sregH, ep_cur, mu_new, lane, C.Ls);
            out[OFF_Z + bt * 32u + lane] = z_own;
            C.zs[lane] = z_own;
            mu_own = mu_new;
            ep_cur = ep_nxt; u_cur = u_nxt;
        } else {
#pragma unroll
            for (int m = 0; m < 6; ++m) gha[m] = sh.w.bhs[lane + 32 * m];
#pragma unroll 4
            for (int hh = 0; hh < 32; ++hh) {
                float hv = __shfl_sync(FULLMASK, hown0, hh);
                const float* wr = &sh.w.Wh[hh * 192 + lane];
#pragma unroll
                for (int m = 0; m < 6; ++m) gha[m] = fmaf(hv, wr[32 * m], gha[m]);
            }
#pragma unroll 4
            for (int hh = 0; hh < 32; ++hh) {
                float hv = __shfl_sync(FULLMASK, hown1, hh);
                const float* wr = &sh.w.Wh[(hh + 32) * 192 + lane];
#pragma unroll
                for (int m = 0; m < 6; ++m) gha[m] = fmaf(hv, wr[32 * m], gha[m]);
            }
        }
        CBAR();

        // ===== P3: spine a_t; helper gx + GRU + softmax ========================
        if (cw == 0) {
            float acc = 0.f;
#pragma unroll
            for (int k = 0; k < 32; ++k) {
                float zk = __shfl_sync(FULLMASK, z_own, k);
                acc = fmaf(C.Cts[k * 17 + (lane & 15)], zk, acc);
            }
            if (lane < 16) out[OFF_A + bt * 16u + lane] = acc;
        } else {
            float z1 = C.zs[lane];
            float gxa[6];
#pragma unroll
            for (int m = 0; m < 6; ++m) gxa[m] = sh.w.bxs[lane + 32 * m];
#pragma unroll 4
            for (int k = 0; k < 32; ++k) {
                float zk = __shfl_sync(FULLMASK, z1, k);
                const float* wr = &sh.w.Wx[k * 192 + lane];
#pragma unroll
                for (int m = 0; m < 6; ++m) gxa[m] = fmaf(zk, wr[32 * m], gxa[m]);
            }
            float r0 = fast_sigmoid(gxa[0] + gha[0]);
            float r1 = fast_sigmoid(gxa[1] + gha[1]);
            float zg0 = fast_sigmoid(gxa[2] + gha[2]);
            float zg1 = fast_sigmoid(gxa[3] + gha[3]);
            float n0 = fast_tanh(gxa[4] + r0 * gha[4]);
            float n1 = fast_tanh(gxa[5] + r1 * gha[5]);
            hown0 = (1.f - zg0) * n0 + zg0 * hown0;
            hown1 = (1.f - zg1) * n1 + zg1 * hown1;
            float4 w0 = sh.w.Wo4[lane], w1 = sh.w.Wo4[lane + 32];
            float p0 = fmaf(hown0, w0.x, hown1 * w1.x);
            float p1 = fmaf(hown0, w0.y, hown1 * w1.y);
            float p2 = fmaf(hown0, w0.z, hown1 * w1.z);
            float p3 = fmaf(hown0, w0.w, hown1 * w1.w);
#pragma unroll
            for (int off = 16; off; off >>= 1) {
                p0 += __shfl_xor_sync(FULLMASK, p0, off);
                p1 += __shfl_xor_sync(FULLMASK, p1, off);
                p2 += __shfl_xor_sync(FULLMASK, p2, off);
                p3 += __shfl_xor_sync(FULLMASK, p3, off);
            }
            float o0 = p0 + bo0, o1 = p1 + bo1, o2 = p2 + bo2, o3 = p3 + bo3;
            float mx = fmaxf(fmaxf(o0, o1), fmaxf(o2, o3));
            float e0 = __expf(o0 - mx), e1 = __expf(o1 - mx);
            float e2 = __expf(o2 - mx), e3 = __expf(o3 - mx);
            float inv = 1.f / (e0 + e1 + e2 + e3);
            if (lane == 0) {
                C.alsh[0] = e0 * inv; C.alsh[1] = e1 * inv;
                C.alsh[2] = e2 * inv; C.alsh[3] = e3 * inv;
            }
        }
        CBAR();
        al0 = C.alsh[0]; al1 = C.alsh[1]; al2 = C.alsh[2]; al3 = C.alsh[3];
    }
#undef CBAR
}

extern "C" void kernel_launch(void* const* d_in, const int* in_sizes, int n_in,
                              void* d_out, int out_size)
{
    size_t shbytes = sizeof(SAll);
    cudaFuncSetAttribute(lgssm_kernel,
                         cudaFuncAttributeMaxDynamicSharedMemorySize, (int)shbytes);
    lgssm_kernel<<<128, 128, shbytes>>>(
        (const float*)d_in[0],  (const float*)d_in[1],  (const float*)d_in[2],
        (const float*)d_in[3],  (const float*)d_in[4],  (const float*)d_in[5],
        (const float*)d_in[6],  (const float*)d_in[7],  (const float*)d_in[8],
        (const float*)d_in[9],  (const float*)d_in[10], (const float*)d_in[11],
        (const float*)d_in[12], (const float*)d_in[13], (const float*)d_in[14],
        (const float*)d_in[15], (float*)d_out);
}

// round 13
// speedup vs baseline: 3.1094x; 1.0170x over previous
#include <cuda_runtime.h>

#define TLEN 256
#define FULLMASK 0xffffffffu

#define OFF_Z   0u
#define OFF_MU  2097152u
#define OFF_SIG 4194304u
#define OFF_A   71303168u
#define OFF_AT  72351744u
#define OFF_BT  139460608u
#define OFF_CT  156237824u

struct SW {
    float4 AmT[1024];      // [k*32+row] = (A0..A3)[row][k]
    float4 CmS[512];       // [flat]
    float4 BmS[256];       // [flat]
    float4 BmT[256];       // [j*32+row]
    float  QT[1024];       // [k*32+row] = Q[row][k]
    float4 Wh4[2048];      // [hh*32+lane] = Wh[hh*192+lane + {0,32,64,96}]
    float2 Wh2[2048];      // [hh*32+lane] = Wh[hh*192+lane + {128,160}]
    float4 Wx4[1024];      // [k*32+lane]  = Wx[k*192+lane + {0,32,64,96}]
    float2 Wx2[1024];      // [k*32+lane]  = Wx[k*192+lane + {128,160}]
    float4 Wo4[64];
    float  bhs[192], bxs[192];
};
struct SC {
    float Ls[32 * 36];     // L rows (float4 pad)
    float Gs[32 * 36];     // G rows
    float As4[32 * 36];    // A_t rows, float4 hand-off
    float Ss1[32 * 36];    // helper's S partial (k<16), float4 hand-off
    float Cts[32 * 17];    // [c*17+r] = C_t[r][c]
    float zs[32];
    float alsh[4];
};
struct SAll { SW w; SC c[2]; };

__device__ __forceinline__ float fast_tanh(float x) {
    float y; asm("tanh.approx.f32 %0, %1;" : "=f"(y) : "f"(x)); return y;
}
__device__ __forceinline__ float fast_sigmoid(float x) {
    return 0.5f + 0.5f * fast_tanh(0.5f * x);
}
__device__ __forceinline__ float mix4(float4 v, float a0, float a1, float a2, float a3) {
    return fmaf(v.x, a0, fmaf(v.y, a1, fmaf(v.z, a2, v.w * a3)));
}

// Fully-unrolled warp Cholesky; a[] in registers throughout.
__device__ __forceinline__ float chol_ls(float a[32], float eps_own, float zinit,
                                         int lane, float* Ls)
{
    float zacc = zinit;
#pragma unroll
    for (int j = 0; j < 32; ++j) {
        float d   = __shfl_sync(FULLMASK, a[j], j);
        float rs  = rsqrtf(d);
        float lij = a[j] * rs;
        a[j] = lij;
        float ej = __shfl_sync(FULLMASK, eps_own, j);
        if (lane >= j) zacc = fmaf(lij, ej, zacc);
        float lsq = lij * lij;
#pragma unroll
        for (int k = j + 1; k < 32; ++k) {
            float lkj = __shfl_sync(FULLMASK, lij, k);
            if (k == lane) a[k] -= lsq;
            else           a[k] = fmaf(-lij, lkj, a[k]);
        }
    }
#pragma unroll
    for (int k = 0; k < 32; ++k) if (k > lane) a[k] = 0.f;
#pragma unroll
    for (int i = 0; i < 8; ++i)
        *(float4*)&Ls[lane * 36 + 4 * i] =
            make_float4(a[4*i], a[4*i+1], a[4*i+2], a[4*i+3]);
    return zacc;
}

__global__ void __launch_bounds__(128, 1)
lgssm_kernel(const float* __restrict__ mu0,   const float* __restrict__ Sig0,
             const float* __restrict__ alpha0,const float* __restrict__ h0,
             const float* __restrict__ u_f,   const float* __restrict__ eps_g,
             const float* __restrict__ Ab,    const float* __restrict__ Bb,
             const float* __restrict__ Cb,    const float* __restrict__ Qm,
             const float* __restrict__ Wx,    const float* __restrict__ Wh,
             const float* __restrict__ bx,    const float* __restrict__ bh,
             const float* __restrict__ Wo,    const float* __restrict__ bo,
             float* __restrict__ out)
{
    extern __shared__ float smem_f[];
    SAll& sh = *reinterpret_cast<SAll*>(smem_f);

    const int tid   = threadIdx.x;
    const int lane  = tid & 31;
    const int wid   = tid >> 5;
    const int chain = wid >> 1;
    const int cw    = wid & 1;          // 0 = spine (chol), 1 = helper
    const int barid = chain + 1;
    SC& C = sh.c[chain];
    const unsigned b = (unsigned)blockIdx.x * 2u + (unsigned)chain;

#define CBAR() asm volatile("bar.sync %0, 64;" :: "r"(barid) : "memory")

    // ---- one-time weight tables ---------------------------------------------
    for (int i = tid; i < 1024; i += 128) {
        int k = i >> 5, row = i & 31, e = row * 32 + k;
        sh.w.AmT[i] = make_float4(Ab[e], Ab[1024 + e], Ab[2048 + e], Ab[3072 + e]);
        sh.w.QT[i]  = Qm[e];
    }
    for (int i = tid; i < 512; i += 128)
        sh.w.CmS[i] = make_float4(Cb[i], Cb[512 + i], Cb[1024 + i], Cb[1536 + i]);
    for (int i = tid; i < 256; i += 128) {
        sh.w.BmS[i] = make_float4(Bb[i], Bb[256 + i], Bb[512 + i], Bb[768 + i]);
        int j = i >> 5, row = i & 31, e = row * 8 + j;
        sh.w.BmT[i] = make_float4(Bb[e], Bb[256 + e], Bb[512 + e], Bb[768 + e]);
    }
    for (int i = tid; i < 2048; i += 128) {
        int hh = i >> 5, l = i & 31, e = hh * 192 + l;
        sh.w.Wh4[i] = make_float4(Wh[e], Wh[e + 32], Wh[e + 64], Wh[e + 96]);
        sh.w.Wh2[i] = make_float2(Wh[e + 128], Wh[e + 160]);
    }
    for (int i = tid; i < 1024; i += 128) {
        int k = i >> 5, l = i & 31, e = k * 192 + l;
        sh.w.Wx4[i] = make_float4(Wx[e], Wx[e + 32], Wx[e + 64], Wx[e + 96]);
        sh.w.Wx2[i] = make_float2(Wx[e + 128], Wx[e + 160]);
    }
    if (tid < 64) sh.w.Wo4[tid] = make_float4(Wo[tid*4], Wo[tid*4+1], Wo[tid*4+2], Wo[tid*4+3]);
    for (int i = tid; i < 192; i += 128) { sh.w.bhs[i] = bh[i]; sh.w.bxs[i] = bx[i]; }

    // ---- per-chain state -----------------------------------------------------
    float al0 = alpha0[b*4u+0], al1 = alpha0[b*4u+1];
    float al2 = alpha0[b*4u+2], al3 = alpha0[b*4u+3];
    float mu_own = 0.f, ep_cur = 0.f, u_cur = 0.f;
    float hown0 = 0.f, hown1 = 0.f, bo0 = 0.f, bo1 = 0.f, bo2 = 0.f, bo3 = 0.f;
    float qrow[32];

    if (cw == 0) {
        mu_own = mu0[b * 32u + lane];
        ep_cur = eps_g[(b * TLEN) * 32u + lane];
        u_cur  = (lane < 8) ? u_f[(b * TLEN) * 8u + lane] : 0.f;
    } else {
        hown0 = h0[b*64u + lane]; hown1 = h0[b*64u + 32 + lane];
        bo0 = bo[0]; bo1 = bo[1]; bo2 = bo[2]; bo3 = bo[3];
    }
    __syncthreads();
    if (cw == 0) {
#pragma unroll
        for (int k = 0; k < 32; ++k) qrow[k] = sh.w.QT[k * 32 + lane];
        float a[32];
#pragma unroll
        for (int i = 0; i < 8; ++i) {
            float4 v = *(const float4*)(Sig0 + b * 1024u + (unsigned)(lane * 32 + 4 * i));
            a[4*i] = v.x; a[4*i+1] = v.y; a[4*i+2] = v.z; a[4*i+3] = v.w;
        }
        (void)chol_ls(a, 0.f, 0.f, lane, C.Ls);
    }
    __syncthreads();

#pragma unroll 1
    for (int t = 0; t < TLEN; ++t) {
        const unsigned bt  = b * TLEN + (unsigned)t;
        const unsigned btn = bt + (t < TLEN - 1 ? 1u : 0u);
        float ar[32], g[16], sregH[32], gha[6];
        float mu_new = 0.f, z_own = 0.f, ep_nxt = 0.f, u_nxt = 0.f;

        // ===== P0: spine A-mixture (regs + As4); helper C/B mixtures ==========
        if (cw == 0) {
            ep_nxt = eps_g[btn * 32u + lane];
            u_nxt  = (lane < 8) ? u_f[btn * 8u + lane] : 0.f;
#pragma unroll
            for (int k = 0; k < 32; ++k)
                ar[k] = mix4(sh.w.AmT[k * 32 + lane], al0, al1, al2, al3);
#pragma unroll
            for (int i = 0; i < 8; ++i)
                *(float4*)&C.As4[lane * 36 + 4 * i] =
                    make_float4(ar[4*i], ar[4*i+1], ar[4*i+2], ar[4*i+3]);
        } else {
#pragma unroll
            for (int e = 0; e < 16; ++e) {
                float cv = mix4(sh.w.CmS[e * 32 + lane], al0, al1, al2, al3);
                C.Cts[lane * 17 + e] = cv;
                out[OFF_CT + bt * 512u + (unsigned)(e * 32 + lane)] = cv;
            }
#pragma unroll
            for (int e = 0; e < 8; ++e)
                out[OFF_BT + bt * 256u + (unsigned)(e * 32 + lane)] =
                    mix4(sh.w.BmS[e * 32 + lane], al0, al1, al2, al3);
        }
        CBAR();

        // ===== P1: spine mu + A_t(regs) + G-high + S-high; helper G/S-low =====
        if (cw == 0) {
            float m0 = 0.f, m1 = 0.f;
#pragma unroll
            for (int k = 0; k < 32; k += 2) {
                m0 = fmaf(ar[k],     __shfl_sync(FULLMASK, mu_own, k),     m0);
                m1 = fmaf(ar[k + 1], __shfl_sync(FULLMASK, mu_own, k + 1), m1);
            }
#pragma unroll
            for (int j = 0; j < 8; ++j) {
                float bj = mix4(sh.w.BmT[j * 32 + lane], al0, al1, al2, al3);
                m0 = fmaf(bj, __shfl_sync(FULLMASK, u_cur, j), m0);
            }
            mu_new = m0 + m1;
            out[OFF_MU + bt * 32u + lane] = mu_new;
#pragma unroll
            for (int i = 0; i < 8; ++i)        // A_t out from registers
                *(float4*)(out + OFF_AT + bt * 1024u + (unsigned)(lane * 32 + 4 * i)) =
                    make_float4(ar[4*i], ar[4*i+1], ar[4*i+2], ar[4*i+3]);
            // G cols 16..31 (triangular: k >= 16+4jb)
#pragma unroll
            for (int i = 0; i < 16; ++i) g[i] = 0.f;
#pragma unroll
            for (int jb = 0; jb < 4; ++jb) {
#pragma unroll
                for (int k = 16 + 4 * jb; k < 32; ++k) {
                    float ak = ar[k];
                    float4 lv = *(const float4*)&C.Ls[k * 36 + 16 + 4 * jb];
                    g[4*jb+0] = fmaf(ak, lv.x, g[4*jb+0]);
                    g[4*jb+1] = fmaf(ak, lv.y, g[4*jb+1]);
                    g[4*jb+2] = fmaf(ak, lv.z, g[4*jb+2]);
                    g[4*jb+3] = fmaf(ak, lv.w, g[4*jb+3]);
                }
            }
#pragma unroll
            for (int i = 0; i < 4; ++i)
                *(float4*)&C.Gs[lane * 36 + 16 + 4 * i] =
                    make_float4(g[4*i], g[4*i+1], g[4*i+2], g[4*i+3]);
            __syncwarp();
#pragma unroll
            for (int j = 0; j < 32; ++j) {     // S-high partial, Q folded into a0
                const float4* Gr = (const float4*)&C.Gs[j * 36 + 16];
                float a0 = qrow[j], a1 = 0.f, a2 = 0.f, a3 = 0.f;
#pragma unroll
                for (int i = 0; i < 4; ++i) {
                    float4 gv = Gr[i];
                    a0 = fmaf(g[4*i+0], gv.x, a0);
                    a1 = fmaf(g[4*i+1], gv.y, a1);
                    a2 = fmaf(g[4*i+2], gv.z, a2);
                    a3 = fmaf(g[4*i+3], gv.w, a3);
                }
                sregH[j] = (a0 + a1) + (a2 + a3);
            }
        } else {
            float ar2[32];
#pragma unroll
            for (int i = 0; i < 8; ++i) {      // own A_t row via float4
                float4 v = *(const float4*)&C.As4[lane * 36 + 4 * i];
                ar2[4*i] = v.x; ar2[4*i+1] = v.y; ar2[4*i+2] = v.z; ar2[4*i+3] = v.w;
            }
            // G cols 0..15 (k >= 4jb)
#pragma unroll
            for (int i = 0; i < 16; ++i) g[i] = 0.f;
#pragma unroll
            for (int jb = 0; jb < 4; ++jb) {
#pragma unroll
                for (int k = 4 * jb; k < 32; ++k) {
                    float ak = ar2[k];
                    float4 lv = *(const float4*)&C.Ls[k * 36 + 4 * jb];
                    g[4*jb+0] = fmaf(ak, lv.x, g[4*jb+0]);
                    g[4*jb+1] = fmaf(ak, lv.y, g[4*jb+1]);
                    g[4*jb+2] = fmaf(ak, lv.z, g[4*jb+2]);
                    g[4*jb+3] = fmaf(ak, lv.w, g[4*jb+3]);
                }
            }
#pragma unroll
            for (int i = 0; i < 4; ++i)
                *(float4*)&C.Gs[lane * 36 + 4 * i] =
                    make_float4(g[4*i], g[4*i+1], g[4*i+2], g[4*i+3]);
            __syncwarp();
            float sregL[32];
#pragma unroll
            for (int j = 0; j < 32; ++j) {     // S-low partial
                const float4* Gr = (const float4*)&C.Gs[j * 36];
                float a0 = 0.f, a1 = 0.f, a2 = 0.f, a3 = 0.f;
#pragma unroll
                for (int i = 0; i < 4; ++i) {
                    float4 gv = Gr[i];
                    a0 = fmaf(g[4*i+0], gv.x, a0);
                    a1 = fmaf(g[4*i+1], gv.y, a1);
                    a2 = fmaf(g[4*i+2], gv.z, a2);
                    a3 = fmaf(g[4*i+3], gv.w, a3);
                }
                sregL[j] = (a0 + a1) + (a2 + a3);
            }
#pragma unroll
            for (int i = 0; i < 8; ++i)
                *(float4*)&C.Ss1[lane * 36 + 4 * i] =
                    make_float4(sregL[4*i], sregL[4*i+1], sregL[4*i+2], sregL[4*i+3]);
        }
        CBAR();

        // ===== P2: spine S assemble + Sigma out + chol; helper gh =============
        if (cw == 0) {
#pragma unroll
            for (int i = 0; i < 8; ++i) {
                float4 v = *(const float4*)&C.Ss1[lane * 36 + 4 * i];
                sregH[4*i+0] += v.x; sregH[4*i+1] += v.y;
                sregH[4*i+2] += v.z; sregH[4*i+3] += v.w;
            }
#pragma unroll
            for (int i = 0; i < 8; ++i)        // Sigma out (symmetric, row-major)
                *(float4*)(out + OFF_SIG + bt * 1024u + (unsigned)(lane * 32 + 4 * i)) =
                    make_float4(sregH[4*i], sregH[4*i+1], sregH[4*i+2], sregH[4*i+3]);
            z_own = chol_ls(sregH, ep_cur, mu_new, lane, C.Ls);
            out[OFF_Z + bt * 32u + lane] = z_own;
            C.zs[lane] = z_own;
            mu_own = mu_new;
            ep_cur = ep_nxt; u_cur = u_nxt;
        } else {
#pragma unroll
            for (int m = 0; m < 6; ++m) gha[m] = sh.w.bhs[lane + 32 * m];
#pragma unroll 4
            for (int hh = 0; hh < 32; ++hh) {
                float hv = __shfl_sync(FULLMASK, hown0, hh);
                float4 w4 = sh.w.Wh4[hh * 32 + lane];
                float2 w2 = sh.w.Wh2[hh * 32 + lane];
                gha[0] = fmaf(hv, w4.x, gha[0]); gha[1] = fmaf(hv, w4.y, gha[1]);
                gha[2] = fmaf(hv, w4.z, gha[2]); gha[3] = fmaf(hv, w4.w, gha[3]);
                gha[4] = fmaf(hv, w2.x, gha[4]); gha[5] = fmaf(hv, w2.y, gha[5]);
            }
#pragma unroll 4
            for (int hh = 0; hh < 32; ++hh) {
                float hv = __shfl_sync(FULLMASK, hown1, hh);
                float4 w4 = sh.w.Wh4[(hh + 32) * 32 + lane];
                float2 w2 = sh.w.Wh2[(hh + 32) * 32 + lane];
                gha[0] = fmaf(hv, w4.x, gha[0]); gha[1] = fmaf(hv, w4.y, gha[1]);
                gha[2] = fmaf(hv, w4.z, gha[2]); gha[3] = fmaf(hv, w4.w, gha[3]);
                gha[4] = fmaf(hv, w2.x, gha[4]); gha[5] = fmaf(hv, w2.y, gha[5]);
            }
        }
        CBAR();

        // ===== P3: spine a_t; helper gx + GRU + softmax ========================
        if (cw == 0) {
            float acc = 0.f;
#pragma unroll
            for (int k = 0; k < 32; ++k) {
                float zk = __shfl_sync(FULLMASK, z_own, k);
                acc = fmaf(C.Cts[k * 17 + (lane & 15)], zk, acc);
            }
            if (lane < 16) out[OFF_A + bt * 16u + lane] = acc;
        } else {
            float z1 = C.zs[lane];
            float gxa[6];
#pragma unroll
            for (int m = 0; m < 6; ++m) gxa[m] = sh.w.bxs[lane + 32 * m];
#pragma unroll 4
            for (int k = 0; k < 32; ++k) {
                float zk = __shfl_sync(FULLMASK, z1, k);
                float4 w4 = sh.w.Wx4[k * 32 + lane];
                float2 w2 = sh.w.Wx2[k * 32 + lane];
                gxa[0] = fmaf(zk, w4.x, gxa[0]); gxa[1] = fmaf(zk, w4.y, gxa[1]);
                gxa[2] = fmaf(zk, w4.z, gxa[2]); gxa[3] = fmaf(zk, w4.w, gxa[3]);
                gxa[4] = fmaf(zk, w2.x, gxa[4]); gxa[5] = fmaf(zk, w2.y, gxa[5]);
            }
            float r0 = fast_sigmoid(gxa[0] + gha[0]);
            float r1 = fast_sigmoid(gxa[1] + gha[1]);
            float zg0 = fast_sigmoid(gxa[2] + gha[2]);
            float zg1 = fast_sigmoid(gxa[3] + gha[3]);
            float n0 = fast_tanh(gxa[4] + r0 * gha[4]);
            float n1 = fast_tanh(gxa[5] + r1 * gha[5]);
            hown0 = (1.f - zg0) * n0 + zg0 * hown0;
            hown1 = (1.f - zg1) * n1 + zg1 * hown1;
            float4 w0 = sh.w.Wo4[lane], w1 = sh.w.Wo4[lane + 32];
            float p0 = fmaf(hown0, w0.x, hown1 * w1.x);
            float p1 = fmaf(hown0, w0.y, hown1 * w1.y);
            float p2 = fmaf(hown0, w0.z, hown1 * w1.z);
            float p3 = fmaf(hown0, w0.w, hown1 * w1.w);
#pragma unroll
            for (int off = 16; off; off >>= 1) {
                p0 += __shfl_xor_sync(FULLMASK, p0, off);
                p1 += __shfl_xor_sync(FULLMASK, p1, off);
                p2 += __shfl_xor_sync(FULLMASK, p2, off);
                p3 += __shfl_xor_sync(FULLMASK, p3, off);
            }
            float o0 = p0 + bo0, o1 = p1 + bo1, o2 = p2 + bo2, o3 = p3 + bo3;
            float mx = fmaxf(fmaxf(o0, o1), fmaxf(o2, o3));
            float e0 = __expf(o0 - mx), e1 = __expf(o1 - mx);
            float e2 = __expf(o2 - mx), e3 = __expf(o3 - mx);
            float inv = 1.f / (e0 + e1 + e2 + e3);
            if (lane == 0) {
                C.alsh[0] = e0 * inv; C.alsh[1] = e1 * inv;
                C.alsh[2] = e2 * inv; C.alsh[3] = e3 * inv;
            }
        }
        CBAR();
        al0 = C.alsh[0]; al1 = C.alsh[1]; al2 = C.alsh[2]; al3 = C.alsh[3];
    }
#undef CBAR
}

extern "C" void kernel_launch(void* const* d_in, const int* in_sizes, int n_in,
                              void* d_out, int out_size)
{
    size_t shbytes = sizeof(SAll);
    cudaFuncSetAttribute(lgssm_kernel,
                         cudaFuncAttributeMaxDynamicSharedMemorySize, (int)shbytes);
    lgssm_kernel<<<128, 128, shbytes>>>(
        (const float*)d_in[0],  (const float*)d_in[1],  (const float*)d_in[2],
        (const float*)d_in[3],  (const float*)d_in[4],  (const float*)d_in[5],
        (const float*)d_in[6],  (const float*)d_in[7],  (const float*)d_in[8],
        (const float*)d_in[9],  (const float*)d_in[10], (const float*)d_in[11],
        (const float*)d_in[12], (const float*)d_in[13], (const float*)d_in[14],
        (const float*)d_in[15], (float*)d_out);
}

// round 14
// speedup vs baseline: 3.1505x; 1.0132x over previous
#include <cuda_runtime.h>

#define TLEN 256
#define FULLMASK 0xffffffffu

#define OFF_Z   0u
#define OFF_MU  2097152u
#define OFF_SIG 4194304u
#define OFF_A   71303168u
#define OFF_AT  72351744u
#define OFF_BT  139460608u
#define OFF_CT  156237824u

struct SW {
    float4 AmT[1024];      // [k*32+row] = (A0..A3)[row][k]
    float4 CmS[512];       // [flat]
    float4 BmS[256];       // [flat]
    float4 BmT[256];       // [j*32+row]
    float  QT[1024];       // [k*32+row] = Q[row][k]
    float4 Wh4[2048];      // [hh*32+lane] = Wh[hh*192+lane + {0,32,64,96}]
    float2 Wh2[2048];      // [hh*32+lane] = Wh[hh*192+lane + {128,160}]
    float4 Wx4[1024];      // [k*32+lane]  = Wx[k*192+lane + {0,32,64,96}]
    float2 Wx2[1024];      // [k*32+lane]  = Wx[k*192+lane + {128,160}]
    float4 Wo4[64];
    float  bhs[192], bxs[192];
};
struct SC {
    float Ls[32 * 36];     // L rows (float4 pad)
    float Gs[32 * 36];     // G rows
    float As4[32 * 36];    // A_t rows hand-off
    float Ss1[32 * 36];    // helper's S partial (k<16)
    float Cts[32 * 17];    // [c*17+r] = C_t[r][c]
    float gxs[192];        // spine -> helper gate inputs
    float alsh[4];
};
struct SAll { SW w; SC c[2]; };

__device__ __forceinline__ float fast_tanh(float x) {
    float y; asm("tanh.approx.f32 %0, %1;" : "=f"(y) : "f"(x)); return y;
}
__device__ __forceinline__ float fast_sigmoid(float x) {
    return 0.5f + 0.5f * fast_tanh(0.5f * x);
}
__device__ __forceinline__ float mix4(float4 v, float a0, float a1, float a2, float a3) {
    return fmaf(v.x, a0, fmaf(v.y, a1, fmaf(v.z, a2, v.w * a3)));
}

// Plain warp Cholesky (init only).
__device__ __forceinline__ void chol_init(float a[32], int lane, float* Ls)
{
#pragma unroll
    for (int j = 0; j < 32; ++j) {
        float d   = __shfl_sync(FULLMASK, a[j], j);
        float rs  = rsqrtf(d);
        float lij = a[j] * rs;
        a[j] = lij;
        float lsq = lij * lij;
#pragma unroll
        for (int k = j + 1; k < 32; ++k) {
            float lkj = __shfl_sync(FULLMASK, lij, k);
            if (k == lane) a[k] -= lsq;
            else           a[k] = fmaf(-lij, lkj, a[k]);
        }
    }
#pragma unroll
    for (int k = 0; k < 32; ++k) if (k > lane) a[k] = 0.f;
#pragma unroll
    for (int i = 0; i < 8; ++i)
        *(float4*)&Ls[lane * 36 + 4 * i] =
            make_float4(a[4*i], a[4*i+1], a[4*i+2], a[4*i+3]);
}

__global__ void __launch_bounds__(128, 1)
lgssm_kernel(const float* __restrict__ mu0,   const float* __restrict__ Sig0,
             const float* __restrict__ alpha0,const float* __restrict__ h0,
             const float* __restrict__ u_f,   const float* __restrict__ eps_g,
             const float* __restrict__ Ab,    const float* __restrict__ Bb,
             const float* __restrict__ Cb,    const float* __restrict__ Qm,
             const float* __restrict__ Wx,    const float* __restrict__ Wh,
             const float* __restrict__ bx,    const float* __restrict__ bh,
             const float* __restrict__ Wo,    const float* __restrict__ bo,
             float* __restrict__ out)
{
    extern __shared__ float smem_f[];
    SAll& sh = *reinterpret_cast<SAll*>(smem_f);

    const int tid   = threadIdx.x;
    const int lane  = tid & 31;
    const int wid   = tid >> 5;
    const int chain = wid >> 1;
    const int cw    = wid & 1;          // 0 = spine (chol), 1 = helper
    const int barid = chain + 1;
    SC& C = sh.c[chain];
    const unsigned b = (unsigned)blockIdx.x * 2u + (unsigned)chain;

#define CBAR() asm volatile("bar.sync %0, 64;" :: "r"(barid) : "memory")

    // ---- one-time weight tables ---------------------------------------------
    for (int i = tid; i < 1024; i += 128) {
        int k = i >> 5, row = i & 31, e = row * 32 + k;
        sh.w.AmT[i] = make_float4(Ab[e], Ab[1024 + e], Ab[2048 + e], Ab[3072 + e]);
        sh.w.QT[i]  = Qm[e];
    }
    for (int i = tid; i < 512; i += 128)
        sh.w.CmS[i] = make_float4(Cb[i], Cb[512 + i], Cb[1024 + i], Cb[1536 + i]);
    for (int i = tid; i < 256; i += 128) {
        sh.w.BmS[i] = make_float4(Bb[i], Bb[256 + i], Bb[512 + i], Bb[768 + i]);
        int j = i >> 5, row = i & 31, e = row * 8 + j;
        sh.w.BmT[i] = make_float4(Bb[e], Bb[256 + e], Bb[512 + e], Bb[768 + e]);
    }
    for (int i = tid; i < 2048; i += 128) {
        int hh = i >> 5, l = i & 31, e = hh * 192 + l;
        sh.w.Wh4[i] = make_float4(Wh[e], Wh[e + 32], Wh[e + 64], Wh[e + 96]);
        sh.w.Wh2[i] = make_float2(Wh[e + 128], Wh[e + 160]);
    }
    for (int i = tid; i < 1024; i += 128) {
        int k = i >> 5, l = i & 31, e = k * 192 + l;
        sh.w.Wx4[i] = make_float4(Wx[e], Wx[e + 32], Wx[e + 64], Wx[e + 96]);
        sh.w.Wx2[i] = make_float2(Wx[e + 128], Wx[e + 160]);
    }
    if (tid < 64) sh.w.Wo4[tid] = make_float4(Wo[tid*4], Wo[tid*4+1], Wo[tid*4+2], Wo[tid*4+3]);
    for (int i = tid; i < 192; i += 128) { sh.w.bhs[i] = bh[i]; sh.w.bxs[i] = bx[i]; }

    // ---- per-chain state -----------------------------------------------------
    float al0 = alpha0[b*4u+0], al1 = alpha0[b*4u+1];
    float al2 = alpha0[b*4u+2], al3 = alpha0[b*4u+3];
    float mu_own = 0.f, ep_cur = 0.f, u_cur = 0.f;
    float hown0 = 0.f, hown1 = 0.f, bo0 = 0.f, bo1 = 0.f, bo2 = 0.f, bo3 = 0.f;

    if (cw == 0) {
        mu_own = mu0[b * 32u + lane];
        ep_cur = eps_g[(b * TLEN) * 32u + lane];
        u_cur  = (lane < 8) ? u_f[(b * TLEN) * 8u + lane] : 0.f;
    } else {
        hown0 = h0[b*64u + lane]; hown1 = h0[b*64u + 32 + lane];
        bo0 = bo[0]; bo1 = bo[1]; bo2 = bo[2]; bo3 = bo[3];
    }
    __syncthreads();
    if (cw == 0) {
        float a[32];
#pragma unroll
        for (int i = 0; i < 8; ++i) {
            float4 v = *(const float4*)(Sig0 + b * 1024u + (unsigned)(lane * 32 + 4 * i));
            a[4*i] = v.x; a[4*i+1] = v.y; a[4*i+2] = v.z; a[4*i+3] = v.w;
        }
        chol_init(a, lane, C.Ls);
    }
    __syncthreads();

#pragma unroll 1
    for (int t = 0; t < TLEN; ++t) {
        const unsigned bt  = b * TLEN + (unsigned)t;
        const unsigned btn = bt + (t < TLEN - 1 ? 1u : 0u);
        float ar[32], g[16], sregH[32], gha[6];
        float mu_new = 0.f, ep_nxt = 0.f, u_nxt = 0.f;

        // ===== P0: spine A-mixture; helper C/B mixtures ========================
        if (cw == 0) {
            ep_nxt = eps_g[btn * 32u + lane];
            u_nxt  = (lane < 8) ? u_f[btn * 8u + lane] : 0.f;
#pragma unroll
            for (int k = 0; k < 32; ++k)
                ar[k] = mix4(sh.w.AmT[k * 32 + lane], al0, al1, al2, al3);
#pragma unroll
            for (int i = 0; i < 8; ++i)
                *(float4*)&C.As4[lane * 36 + 4 * i] =
                    make_float4(ar[4*i], ar[4*i+1], ar[4*i+2], ar[4*i+3]);
        } else {
#pragma unroll
            for (int e = 0; e < 16; ++e) {
                float cv = mix4(sh.w.CmS[e * 32 + lane], al0, al1, al2, al3);
                C.Cts[lane * 17 + e] = cv;
                out[OFF_CT + bt * 512u + (unsigned)(e * 32 + lane)] = cv;
            }
#pragma unroll
            for (int e = 0; e < 8; ++e)
                out[OFF_BT + bt * 256u + (unsigned)(e * 32 + lane)] =
                    mix4(sh.w.BmS[e * 32 + lane], al0, al1, al2, al3);
        }
        CBAR();

        // ===== P1: spine mu + A_t + G-high + S-high; helper G-low + S-low =====
        if (cw == 0) {
            float m0 = 0.f, m1 = 0.f;
#pragma unroll
            for (int k = 0; k < 32; k += 2) {
                m0 = fmaf(ar[k],     __shfl_sync(FULLMASK, mu_own, k),     m0);
                m1 = fmaf(ar[k + 1], __shfl_sync(FULLMASK, mu_own, k + 1), m1);
            }
#pragma unroll
            for (int j = 0; j < 8; ++j) {
                float bj = mix4(sh.w.BmT[j * 32 + lane], al0, al1, al2, al3);
                m0 = fmaf(bj, __shfl_sync(FULLMASK, u_cur, j), m0);
            }
            mu_new = m0 + m1;
            out[OFF_MU + bt * 32u + lane] = mu_new;
#pragma unroll
            for (int i = 0; i < 8; ++i)
                *(float4*)(out + OFF_AT + bt * 1024u + (unsigned)(lane * 32 + 4 * i)) =
                    make_float4(ar[4*i], ar[4*i+1], ar[4*i+2], ar[4*i+3]);
            // G cols 16..31 (triangular: k >= 16+4jb)
#pragma unroll
            for (int i = 0; i < 16; ++i) g[i] = 0.f;
#pragma unroll
            for (int jb = 0; jb < 4; ++jb) {
#pragma unroll
                for (int k = 16 + 4 * jb; k < 32; ++k) {
                    float ak = ar[k];
                    float4 lv = *(const float4*)&C.Ls[k * 36 + 16 + 4 * jb];
                    g[4*jb+0] = fmaf(ak, lv.x, g[4*jb+0]);
                    g[4*jb+1] = fmaf(ak, lv.y, g[4*jb+1]);
                    g[4*jb+2] = fmaf(ak, lv.z, g[4*jb+2]);
                    g[4*jb+3] = fmaf(ak, lv.w, g[4*jb+3]);
                }
            }
#pragma unroll
            for (int i = 0; i < 4; ++i)
                *(float4*)&C.Gs[lane * 36 + 16 + 4 * i] =
                    make_float4(g[4*i], g[4*i+1], g[4*i+2], g[4*i+3]);
            __syncwarp();
#pragma unroll
            for (int j = 0; j < 32; ++j) {     // S-high partial + Q fold
                const float4* Gr = (const float4*)&C.Gs[j * 36 + 16];
                float a0 = sh.w.QT[j * 32 + lane], a1 = 0.f, a2 = 0.f, a3 = 0.f;
#pragma unroll
                for (int i = 0; i < 4; ++i) {
                    float4 gv = Gr[i];
                    a0 = fmaf(g[4*i+0], gv.x, a0);
                    a1 = fmaf(g[4*i+1], gv.y, a1);
                    a2 = fmaf(g[4*i+2], gv.z, a2);
                    a3 = fmaf(g[4*i+3], gv.w, a3);
                }
                sregH[j] = (a0 + a1) + (a2 + a3);
            }
        } else {
            float ar2[32];
#pragma unroll
            for (int i = 0; i < 8; ++i) {
                float4 v = *(const float4*)&C.As4[lane * 36 + 4 * i];
                ar2[4*i] = v.x; ar2[4*i+1] = v.y; ar2[4*i+2] = v.z; ar2[4*i+3] = v.w;
            }
            // G cols 0..15 (k >= 4jb)
#pragma unroll
            for (int i = 0; i < 16; ++i) g[i] = 0.f;
#pragma unroll
            for (int jb = 0; jb < 4; ++jb) {
#pragma unroll
                for (int k = 4 * jb; k < 32; ++k) {
                    float ak = ar2[k];
                    float4 lv = *(const float4*)&C.Ls[k * 36 + 4 * jb];
                    g[4*jb+0] = fmaf(ak, lv.x, g[4*jb+0]);
                    g[4*jb+1] = fmaf(ak, lv.y, g[4*jb+1]);
                    g[4*jb+2] = fmaf(ak, lv.z, g[4*jb+2]);
                    g[4*jb+3] = fmaf(ak, lv.w, g[4*jb+3]);
                }
            }
#pragma unroll
            for (int i = 0; i < 4; ++i)
                *(float4*)&C.Gs[lane * 36 + 4 * i] =
                    make_float4(g[4*i], g[4*i+1], g[4*i+2], g[4*i+3]);
            __syncwarp();
            float sregL[32];
#pragma unroll
            for (int j = 0; j < 32; ++j) {
                const float4* Gr = (const float4*)&C.Gs[j * 36];
                float a0 = 0.f, a1 = 0.f, a2 = 0.f, a3 = 0.f;
#pragma unroll
                for (int i = 0; i < 4; ++i) {
                    float4 gv = Gr[i];
                    a0 = fmaf(g[4*i+0], gv.x, a0);
                    a1 = fmaf(g[4*i+1], gv.y, a1);
                    a2 = fmaf(g[4*i+2], gv.z, a2);
                    a3 = fmaf(g[4*i+3], gv.w, a3);
                }
                sregL[j] = (a0 + a1) + (a2 + a3);
            }
#pragma unroll
            for (int i = 0; i < 8; ++i)
                *(float4*)&C.Ss1[lane * 36 + 4 * i] =
                    make_float4(sregL[4*i], sregL[4*i+1], sregL[4*i+2], sregL[4*i+3]);
        }
        CBAR();

        // ===== P2: spine assemble + Sigma out + FUSED chol(z,gx,a_t); helper gh
        if (cw == 0) {
#pragma unroll
            for (int i = 0; i < 8; ++i) {
                float4 v = *(const float4*)&C.Ss1[lane * 36 + 4 * i];
                sregH[4*i+0] += v.x; sregH[4*i+1] += v.y;
                sregH[4*i+2] += v.z; sregH[4*i+3] += v.w;
            }
#pragma unroll
            for (int i = 0; i < 8; ++i)
                *(float4*)(out + OFF_SIG + bt * 1024u + (unsigned)(lane * 32 + 4 * i)) =
                    make_float4(sregH[4*i], sregH[4*i+1], sregH[4*i+2], sregH[4*i+3]);

            // fused Cholesky: z, gx, a_t accumulated in the d-chain shadows
            float zacc = mu_new;
            float gxa0 = sh.w.bxs[lane],       gxa1 = sh.w.bxs[lane + 32];
            float gxa2 = sh.w.bxs[lane + 64],  gxa3 = sh.w.bxs[lane + 96];
            float gxa4 = sh.w.bxs[lane + 128], gxa5 = sh.w.bxs[lane + 160];
            float at_acc = 0.f;
            const int lr = lane & 15;
#pragma unroll
            for (int j = 0; j < 32; ++j) {
                float d   = __shfl_sync(FULLMASK, sregH[j], j);
                float rs  = rsqrtf(d);
                float lij = sregH[j] * rs;
                sregH[j] = lij;
                float ej = __shfl_sync(FULLMASK, ep_cur, j);
                if (lane >= j) zacc = fmaf(lij, ej, zacc);
                float zj = __shfl_sync(FULLMASK, zacc, j);   // final z[j]
                {
                    float4 w4 = sh.w.Wx4[j * 32 + lane];
                    float2 w2 = sh.w.Wx2[j * 32 + lane];
                    gxa0 = fmaf(zj, w4.x, gxa0); gxa1 = fmaf(zj, w4.y, gxa1);
                    gxa2 = fmaf(zj, w4.z, gxa2); gxa3 = fmaf(zj, w4.w, gxa3);
                    gxa4 = fmaf(zj, w2.x, gxa4); gxa5 = fmaf(zj, w2.y, gxa5);
                    at_acc = fmaf(C.Cts[j * 17 + lr], zj, at_acc);
                }
                float lsq = lij * lij;
#pragma unroll
                for (int k = j + 1; k < 32; ++k) {
                    float lkj = __shfl_sync(FULLMASK, lij, k);
                    if (k == lane) sregH[k] -= lsq;
                    else           sregH[k] = fmaf(-lij, lkj, sregH[k]);
                }
            }
#pragma unroll
            for (int k = 0; k < 32; ++k) if (k > lane) sregH[k] = 0.f;
#pragma unroll
            for (int i = 0; i < 8; ++i)
                *(float4*)&C.Ls[lane * 36 + 4 * i] =
                    make_float4(sregH[4*i], sregH[4*i+1], sregH[4*i+2], sregH[4*i+3]);

            out[OFF_Z + bt * 32u + lane] = zacc;
            if (lane < 16) out[OFF_A + bt * 16u + lane] = at_acc;
            C.gxs[lane]       = gxa0; C.gxs[lane + 32]  = gxa1;
            C.gxs[lane + 64]  = gxa2; C.gxs[lane + 96]  = gxa3;
            C.gxs[lane + 128] = gxa4; C.gxs[lane + 160] = gxa5;
            mu_own = mu_new; ep_cur = ep_nxt; u_cur = u_nxt;
        } else {
#pragma unroll
            for (int m = 0; m < 6; ++m) gha[m] = sh.w.bhs[lane + 32 * m];
#pragma unroll 4
            for (int hh = 0; hh < 32; ++hh) {
                float hv = __shfl_sync(FULLMASK, hown0, hh);
                float4 w4 = sh.w.Wh4[hh * 32 + lane];
                float2 w2 = sh.w.Wh2[hh * 32 + lane];
                gha[0] = fmaf(hv, w4.x, gha[0]); gha[1] = fmaf(hv, w4.y, gha[1]);
                gha[2] = fmaf(hv, w4.z, gha[2]); gha[3] = fmaf(hv, w4.w, gha[3]);
                gha[4] = fmaf(hv, w2.x, gha[4]); gha[5] = fmaf(hv, w2.y, gha[5]);
            }
#pragma unroll 4
            for (int hh = 0; hh < 32; ++hh) {
                float hv = __shfl_sync(FULLMASK, hown1, hh);
                float4 w4 = sh.w.Wh4[(hh + 32) * 32 + lane];
                float2 w2 = sh.w.Wh2[(hh + 32) * 32 + lane];
                gha[0] = fmaf(hv, w4.x, gha[0]); gha[1] = fmaf(hv, w4.y, gha[1]);
                gha[2] = fmaf(hv, w4.z, gha[2]); gha[3] = fmaf(hv, w4.w, gha[3]);
                gha[4] = fmaf(hv, w2.x, gha[4]); gha[5] = fmaf(hv, w2.y, gha[5]);
            }
        }
        CBAR();

        // ===== P3: helper GRU + softmax (spine idles briefly) ==================
        if (cw == 1) {
            float gx0 = C.gxs[lane],       gx1 = C.gxs[lane + 32];
            float gx2 = C.gxs[lane + 64],  gx3 = C.gxs[lane + 96];
            float gx4 = C.gxs[lane + 128], gx5 = C.gxs[lane + 160];
            float r0 = fast_sigmoid(gx0 + gha[0]);
            float r1 = fast_sigmoid(gx1 + gha[1]);
            float zg0 = fast_sigmoid(gx2 + gha[2]);
            float zg1 = fast_sigmoid(gx3 + gha[3]);
            float n0 = fast_tanh(gx4 + r0 * gha[4]);
            float n1 = fast_tanh(gx5 + r1 * gha[5]);
            hown0 = (1.f - zg0) * n0 + zg0 * hown0;
            hown1 = (1.f - zg1) * n1 + zg1 * hown1;
            float4 w0 = sh.w.Wo4[lane], w1 = sh.w.Wo4[lane + 32];
            float p0 = fmaf(hown0, w0.x, hown1 * w1.x);
            float p1 = fmaf(hown0, w0.y, hown1 * w1.y);
            float p2 = fmaf(hown0, w0.z, hown1 * w1.z);
            float p3 = fmaf(hown0, w0.w, hown1 * w1.w);
#pragma unroll
            for (int off = 16; off; off >>= 1) {
                p0 += __shfl_xor_sync(FULLMASK, p0, off);
                p1 += __shfl_xor_sync(FULLMASK, p1, off);
                p2 += __shfl_xor_sync(FULLMASK, p2, off);
                p3 += __shfl_xor_sync(FULLMASK, p3, off);
            }
            float o0 = p0 + bo0, o1 = p1 + bo1, o2 = p2 + bo2, o3 = p3 + bo3;
            float mx = fmaxf(fmaxf(o0, o1), fmaxf(o2, o3));
            float e0 = __expf(o0 - mx), e1 = __expf(o1 - mx);
            float e2 = __expf(o2 - mx), e3 = __expf(o3 - mx);
            float inv = 1.f / (e0 + e1 + e2 + e3);
            if (lane == 0) {
                C.alsh[0] = e0 * inv; C.alsh[1] = e1 * inv;
                C.alsh[2] = e2 * inv; C.alsh[3] = e3 * inv;
            }
        }
        CBAR();
        al0 = C.alsh[0]; al1 = C.alsh[1]; al2 = C.alsh[2]; al3 = C.alsh[3];
    }
#undef CBAR
}

extern "C" void kernel_launch(void* const* d_in, const int* in_sizes, int n_in,
                              void* d_out, int out_size)
{
    size_t shbytes = sizeof(SAll);
    cudaFuncSetAttribute(lgssm_kernel,
                         cudaFuncAttributeMaxDynamicSharedMemorySize, (int)shbytes);
    lgssm_kernel<<<128, 128, shbytes>>>(
        (const float*)d_in[0],  (const float*)d_in[1],  (const float*)d_in[2],
        (const float*)d_in[3],  (const float*)d_in[4],  (const float*)d_in[5],
        (const float*)d_in[6],  (const float*)d_in[7],  (const float*)d_in[8],
        (const float*)d_in[9],  (const float*)d_in[10], (const float*)d_in[11],
        (const float*)d_in[12], (const float*)d_in[13], (const float*)d_in[14],
        (const float*)d_in[15], (float*)d_out);
}